// round 1
// baseline (speedup 1.0000x reference)
#include <cuda_runtime.h>

#define S_LEN   4096
#define DMODEL  1024
#define NHEADS  16
#define DK      64

// Scratch (allocation-free rule: __device__ globals)
__device__ float g_q [S_LEN * DMODEL];
__device__ float g_k [S_LEN * DMODEL];
__device__ float g_v [S_LEN * DMODEL];
__device__ float g_ao[S_LEN * DMODEL];

// ---------------------------------------------------------------------------
// NT GEMM: C[M,N] = A[M,K] * B[N,K]^T   (both A and B are K-major row dots)
// 128x128 tile, BK=8, 256 threads, 8x8 register micro-tile.
// ---------------------------------------------------------------------------
#define BM 128
#define BN 128
#define BKS 8

__global__ void __launch_bounds__(256) gemm_nt(const float* __restrict__ A,
                                               const float* __restrict__ B,
                                               float* __restrict__ C,
                                               int M, int N, int K) {
    __shared__ float As[BKS][BM];
    __shared__ float Bs[BKS][BN];
    const int bm  = blockIdx.y * BM;
    const int bn  = blockIdx.x * BN;
    const int tid = threadIdx.x;
    const int tx  = tid & 15;       // 0..15 -> n micro-tile
    const int ty  = tid >> 4;       // 0..15 -> m micro-tile
    const int lr  = tid >> 1;       // 0..127 row for loads
    const int lc4 = (tid & 1) * 4;  // 0 or 4 (k offset)

    float acc[8][8];
#pragma unroll
    for (int i = 0; i < 8; i++)
#pragma unroll
        for (int j = 0; j < 8; j++) acc[i][j] = 0.f;

    for (int k0 = 0; k0 < K; k0 += BKS) {
        float4 a4 = *(const float4*)(A + (size_t)(bm + lr) * K + k0 + lc4);
        float4 b4 = *(const float4*)(B + (size_t)(bn + lr) * K + k0 + lc4);
        As[lc4 + 0][lr] = a4.x; As[lc4 + 1][lr] = a4.y;
        As[lc4 + 2][lr] = a4.z; As[lc4 + 3][lr] = a4.w;
        Bs[lc4 + 0][lr] = b4.x; Bs[lc4 + 1][lr] = b4.y;
        Bs[lc4 + 2][lr] = b4.z; Bs[lc4 + 3][lr] = b4.w;
        __syncthreads();
#pragma unroll
        for (int kk = 0; kk < BKS; kk++) {
            float ar[8], br[8];
            *(float4*)&ar[0] = *(const float4*)&As[kk][ty * 8];
            *(float4*)&ar[4] = *(const float4*)&As[kk][ty * 8 + 4];
            *(float4*)&br[0] = *(const float4*)&Bs[kk][tx * 8];
            *(float4*)&br[4] = *(const float4*)&Bs[kk][tx * 8 + 4];
#pragma unroll
            for (int i = 0; i < 8; i++)
#pragma unroll
                for (int j = 0; j < 8; j++) acc[i][j] += ar[i] * br[j];
        }
        __syncthreads();
    }
#pragma unroll
    for (int i = 0; i < 8; i++) {
        float* cp = C + (size_t)(bm + ty * 8 + i) * N + bn + tx * 8;
        *(float4*)cp       = make_float4(acc[i][0], acc[i][1], acc[i][2], acc[i][3]);
        *(float4*)(cp + 4) = make_float4(acc[i][4], acc[i][5], acc[i][6], acc[i][7]);
    }
}

// ---------------------------------------------------------------------------
// Flash attention: grid (S/64, H), 256 threads.
// Block = 64 queries x all 4096 keys in 64-key tiles, online softmax.
// Thread (ty,tx) in 16x16 grid owns 4 q-rows x 4 cols.
// SMEM: Qs (Q^T, scaled) + KP (K^T for QK^T, then P[q][t]) + Vs = 48KB exactly.
// ---------------------------------------------------------------------------
__global__ void __launch_bounds__(256) attn_fa(const float* __restrict__ Qg,
                                               const float* __restrict__ Kg,
                                               const float* __restrict__ Vg,
                                               float* __restrict__ Og) {
    __shared__ float Qs[DK][64];   // Qs[d][q]
    __shared__ float KP[DK][64];   // phase A: K^T[d][t]; phase B/C: P[q][t]
    __shared__ float Vs[64][DK];   // Vs[t][d]

    const int h   = blockIdx.y;
    const int q0  = blockIdx.x * 64;
    const int tid = threadIdx.x;
    const int tx  = tid & 15;
    const int ty  = tid >> 4;
    const float scale = 0.125f;    // 1/sqrt(64)

    // Load Q tile transposed + pre-scaled.
    // Index mapping r = i & 63 makes the transposed STS lane-consecutive in r
    // -> conflict-free shared stores (global side is strided but L2-cached).
    for (int i = tid; i < 64 * DK / 4; i += 256) {
        int r  = i & 63;
        int c4 = (i >> 6) * 4;
        float4 t4 = *(const float4*)(Qg + (size_t)(q0 + r) * DMODEL + h * DK + c4);
        Qs[c4 + 0][r] = t4.x * scale; Qs[c4 + 1][r] = t4.y * scale;
        Qs[c4 + 2][r] = t4.z * scale; Qs[c4 + 3][r] = t4.w * scale;
    }

    float m_i[4], l_i[4], o[4][4];
#pragma unroll
    for (int i = 0; i < 4; i++) {
        m_i[i] = -1e30f; l_i[i] = 0.f;
#pragma unroll
        for (int j = 0; j < 4; j++) o[i][j] = 0.f;
    }

    for (int t0 = 0; t0 < S_LEN; t0 += 64) {
        __syncthreads();  // prev-iter P/Vs reads done before overwrite
        // K tile, transposed store (same conflict-free mapping as Q)
        for (int i = tid; i < 64 * DK / 4; i += 256) {
            int r  = i & 63;
            int c4 = (i >> 6) * 4;
            float4 t4 = *(const float4*)(Kg + (size_t)(t0 + r) * DMODEL + h * DK + c4);
            KP[c4 + 0][r] = t4.x; KP[c4 + 1][r] = t4.y;
            KP[c4 + 2][r] = t4.z; KP[c4 + 3][r] = t4.w;
        }
        // V tile, natural layout, coalesced global + conflict-free STS.128
        for (int i = tid; i < 64 * DK / 4; i += 256) {
            int r  = i >> 4;
            int c4 = (i & 15) * 4;
            float4 t4 = *(const float4*)(Vg + (size_t)(t0 + r) * DMODEL + h * DK + c4);
            *(float4*)&Vs[r][c4] = t4;
        }
        __syncthreads();

        // ---- Phase A: S = (Q*scale) K^T, 4x4 per thread ----
        float s[4][4];
#pragma unroll
        for (int i = 0; i < 4; i++)
#pragma unroll
            for (int j = 0; j < 4; j++) s[i][j] = 0.f;
#pragma unroll 8
        for (int d = 0; d < DK; d++) {
            float qa[4], kb[4];
            *(float4*)qa = *(const float4*)&Qs[d][ty * 4];
            *(float4*)kb = *(const float4*)&KP[d][tx * 4];
#pragma unroll
            for (int i = 0; i < 4; i++)
#pragma unroll
                for (int j = 0; j < 4; j++) s[i][j] += qa[i] * kb[j];
        }
        __syncthreads();  // all threads done reading KP as K^T

        // ---- Phase B: online softmax ----
        // Row reductions across the 16 tx threads of each q row; lane = (ty&1)*16+tx,
        // so xor-shuffles with offset<16 stay inside the row group.
        float mt[4];
#pragma unroll
        for (int i = 0; i < 4; i++)
            mt[i] = fmaxf(fmaxf(s[i][0], s[i][1]), fmaxf(s[i][2], s[i][3]));
#pragma unroll
        for (int off = 1; off < 16; off <<= 1)
#pragma unroll
            for (int i = 0; i < 4; i++)
                mt[i] = fmaxf(mt[i], __shfl_xor_sync(0xffffffffu, mt[i], off));

        float corr[4];
#pragma unroll
        for (int i = 0; i < 4; i++) {
            float mn = fmaxf(m_i[i], mt[i]);
            corr[i]  = __expf(m_i[i] - mn);
            m_i[i]   = mn;
        }
        float rs[4];
#pragma unroll
        for (int i = 0; i < 4; i++) {
            rs[i] = 0.f;
#pragma unroll
            for (int j = 0; j < 4; j++) {
                float p = __expf(s[i][j] - m_i[i]);
                KP[ty * 4 + i][tx * 4 + j] = p;   // write P over K^T
                rs[i] += p;
            }
        }
#pragma unroll
        for (int off = 1; off < 16; off <<= 1)
#pragma unroll
            for (int i = 0; i < 4; i++)
                rs[i] += __shfl_xor_sync(0xffffffffu, rs[i], off);
#pragma unroll
        for (int i = 0; i < 4; i++) {
            l_i[i] = l_i[i] * corr[i] + rs[i];
#pragma unroll
            for (int j = 0; j < 4; j++) o[i][j] *= corr[i];
        }
        __syncthreads();  // P visible to all

        // ---- Phase C: O += P V ----
#pragma unroll 8
        for (int kk = 0; kk < 64; kk++) {
            float pv[4], vv[4];
#pragma unroll
            for (int i = 0; i < 4; i++) pv[i] = KP[ty * 4 + i][kk];  // broadcast
            *(float4*)vv = *(const float4*)&Vs[kk][tx * 4];
#pragma unroll
            for (int i = 0; i < 4; i++)
#pragma unroll
                for (int j = 0; j < 4; j++) o[i][j] += pv[i] * vv[j];
        }
    }

    // Normalize + write
#pragma unroll
    for (int i = 0; i < 4; i++) {
        float inv = 1.f / l_i[i];
        float* op = Og + (size_t)(q0 + ty * 4 + i) * DMODEL + h * DK + tx * 4;
        *(float4*)op = make_float4(o[i][0] * inv, o[i][1] * inv,
                                   o[i][2] * inv, o[i][3] * inv);
    }
}

// ---------------------------------------------------------------------------
extern "C" void kernel_launch(void* const* d_in, const int* in_sizes, int n_in,
                              void* d_out, int out_size) {
    const float* x  = (const float*)d_in[0];
    const float* Wq = (const float*)d_in[1];
    const float* Wk = (const float*)d_in[2];
    const float* Wv = (const float*)d_in[3];
    const float* Wo = (const float*)d_in[4];
    float* out = (float*)d_out;

    float *q, *k, *v, *ao;
    cudaGetSymbolAddress((void**)&q,  g_q);
    cudaGetSymbolAddress((void**)&k,  g_k);
    cudaGetSymbolAddress((void**)&v,  g_v);
    cudaGetSymbolAddress((void**)&ao, g_ao);

    dim3 gg(DMODEL / BN, S_LEN / BM);  // (8, 32)
    gemm_nt<<<gg, 256>>>(x, Wq, q, S_LEN, DMODEL, DMODEL);
    gemm_nt<<<gg, 256>>>(x, Wk, k, S_LEN, DMODEL, DMODEL);
    gemm_nt<<<gg, 256>>>(x, Wv, v, S_LEN, DMODEL, DMODEL);

    attn_fa<<<dim3(S_LEN / 64, NHEADS), 256>>>(q, k, v, ao);

    gemm_nt<<<gg, 256>>>(ao, Wo, out, S_LEN, DMODEL, DMODEL);
}